// round 12
// baseline (speedup 1.0000x reference)
#include <cuda_runtime.h>
#include <cstdint>
#include <math_constants.h>

#define B_   16
#define C_   256
#define N_   4096
#define O3_  768
#define HEADS_ 8
#define HD_  32
#define EPS_ 1e-5f

__device__ float g_qkv[(size_t)B_ * O3_ * N_];   // q channels hold tf32-rounded exp(BN(q))
__device__ float g_ctx[(size_t)B_ * HEADS_ * HD_ * HD_];
__device__ float g_M[(size_t)B_ * C_ * C_];      // tf32-rounded proj_w @ ctx / s_c
__device__ float g_ssum[(size_t)B_ * C_];        // s_c = sum_n exp(q[c,n])
__device__ float g_wr[(size_t)O3_ * C_];         // tf32-rounded qkv_w

__device__ __forceinline__ uint32_t smem_u32(const void* p) {
    uint32_t a;
    asm("{ .reg .u64 t; cvta.to.shared.u64 t, %1; cvt.u32.u64 %0, t; }"
        : "=r"(a) : "l"(p));
    return a;
}

__device__ __forceinline__ uint32_t tf32c(float f) {
    uint32_t u;
    asm("cvt.rna.tf32.f32 %0, %1;" : "=r"(u) : "f"(f));
    return u;
}

__device__ __forceinline__ void cp16(uint32_t dst, const void* src) {
    asm volatile("cp.async.cg.shared.global [%0], [%1], 16;" :: "r"(dst), "l"(src));
}
#define CP_COMMIT() asm volatile("cp.async.commit_group;" ::: "memory")
#define CP_WAIT0()  asm volatile("cp.async.wait_group 0;" ::: "memory")

__device__ __forceinline__ void mma_tf32(float* c, uint32_t a0, uint32_t a1,
                                         uint32_t a2, uint32_t a3,
                                         uint32_t b0, uint32_t b1) {
    asm volatile(
        "mma.sync.aligned.m16n8k8.row.col.f32.tf32.tf32.f32 "
        "{%0,%1,%2,%3}, {%4,%5,%6,%7}, {%8,%9}, {%0,%1,%2,%3};"
        : "+f"(c[0]), "+f"(c[1]), "+f"(c[2]), "+f"(c[3])
        : "r"(a0), "r"(a1), "r"(a2), "r"(a3), "r"(b0), "r"(b1));
}

#define KT_   32
#define APAD  36      // floats per A row (32 + 4 pad)
#define BPAD  136     // floats per B row (128 + 8 pad)
#define ABUF  (128 * APAD)
#define BBUF  (KT_ * BPAD)
#define GSMEM ((2 * ABUF + 2 * BBUF) * 4)   // 71680 bytes

extern __shared__ float gem_sm[];

// ---------------------------------------------------------------------------
// tf32 tensor-core GEMM, 128x128 tile, K=256, k-tile 32, 2-stage cp.async.
// tn-outer register blocking; targets 3 CTAs/SM (regs <= 85).
// C[o,n] = BN( sum_k A[o,k] * Bm[k,n] )  per batch (blockIdx.z).
// ---------------------------------------------------------------------------
__global__ __launch_bounds__(256, 3)
void gemm_tc_bn(const float* __restrict__ A, long aStride,
                const float* __restrict__ Bm, long bStride,
                float* __restrict__ Out, long oStride,
                const float* __restrict__ gamma, const float* __restrict__ beta,
                const float* __restrict__ mean,  const float* __restrict__ var,
                int expq, float* __restrict__ ssum)
{
    const int b   = blockIdx.z;
    const int n0c = blockIdx.x * 128;
    const int o0c = blockIdx.y * 128;
    const float* Ab = A  + (size_t)b * aStride;
    const float* Bb = Bm + (size_t)b * bStride;
    float*       Ob = Out + (size_t)b * oStride;

    float* Asm = gem_sm;
    float* Bsm = gem_sm + 2 * ABUF;

    const int t    = threadIdx.x;
    const int wid  = t >> 5;
    const int lane = t & 31;
    const int gid  = lane >> 2;
    const int tig  = lane & 3;
    const int m0   = (wid & 3) * 32;
    const int n0w  = (wid >> 2) * 64;

    const uint32_t smA = smem_u32(Asm);
    const uint32_t smB = smem_u32(Bsm);

    float acc[2][8][4];
#pragma unroll
    for (int tm = 0; tm < 2; tm++)
#pragma unroll
        for (int tn = 0; tn < 8; tn++)
#pragma unroll
            for (int q = 0; q < 4; q++) acc[tm][tn][q] = 0.f;

    // ---- prefetch tile 0 ----
#pragma unroll
    for (int r = 0; r < 4; r++) {
        const int c = t + r * 256;
        const int o = c >> 3, kp = (c & 7) * 4;
        cp16(smA + (uint32_t)(o * APAD + kp) * 4,
             Ab + (size_t)(o0c + o) * 256 + kp);
    }
#pragma unroll
    for (int r = 0; r < 4; r++) {
        const int c = t + r * 256;
        const int k = c >> 5, np = (c & 31) * 4;
        cp16(smB + (uint32_t)(k * BPAD + np) * 4,
             Bb + (size_t)k * N_ + n0c + np);
    }
    CP_COMMIT();

    for (int kt = 0; kt < 8; kt++) {
        CP_WAIT0();
        __syncthreads();

        if (kt < 7) {
            const int k0 = (kt + 1) * KT_;
            const uint32_t bufo = (uint32_t)((kt + 1) & 1);
            const uint32_t dA = smA + bufo * (ABUF * 4);
            const uint32_t dB = smB + bufo * (BBUF * 4);
#pragma unroll
            for (int r = 0; r < 4; r++) {
                const int c = t + r * 256;
                const int o = c >> 3, kp = (c & 7) * 4;
                cp16(dA + (uint32_t)(o * APAD + kp) * 4,
                     Ab + (size_t)(o0c + o) * 256 + k0 + kp);
            }
#pragma unroll
            for (int r = 0; r < 4; r++) {
                const int c = t + r * 256;
                const int k = c >> 5, np = (c & 31) * 4;
                cp16(dB + (uint32_t)(k * BPAD + np) * 4,
                     Bb + (size_t)(k0 + k) * N_ + n0c + np);
            }
            CP_COMMIT();
        }

        const float* As2 = Asm + (kt & 1) * ABUF;
        const float* Bs2 = Bsm + (kt & 1) * BBUF;

#pragma unroll
        for (int ks = 0; ks < 4; ks++) {
            const int kb = ks * 8;
            // A fragments once per ks (8 live regs)
            uint32_t af[2][4];
#pragma unroll
            for (int tm = 0; tm < 2; tm++) {
                const int oa = (m0 + tm * 16 + gid) * APAD;
                const int ob = oa + 8 * APAD;
                af[tm][0] = __float_as_uint(As2[oa + kb + tig]);
                af[tm][1] = __float_as_uint(As2[ob + kb + tig]);
                af[tm][2] = __float_as_uint(As2[oa + kb + tig + 4]);
                af[tm][3] = __float_as_uint(As2[ob + kb + tig + 4]);
            }
            // tn-outer: B fragments transient (2 live regs)
#pragma unroll
            for (int tn = 0; tn < 8; tn++) {
                const uint32_t b0 = __float_as_uint(Bs2[(kb + tig) * BPAD + n0w + tn * 8 + gid]);
                const uint32_t b1 = __float_as_uint(Bs2[(kb + tig + 4) * BPAD + n0w + tn * 8 + gid]);
                mma_tf32(acc[0][tn], af[0][0], af[0][1], af[0][2], af[0][3], b0, b1);
                mma_tf32(acc[1][tn], af[1][0], af[1][1], af[1][2], af[1][3], b0, b1);
            }
        }
    }

    const int doexp = expq && (o0c < 256);

#pragma unroll
    for (int tm = 0; tm < 2; tm++) {
        const int o_a = o0c + m0 + tm * 16 + gid;
        const int o_b = o_a + 8;
        const float sc_a = gamma[o_a] * rsqrtf(var[o_a] + EPS_);
        const float sh_a = beta[o_a] - mean[o_a] * sc_a;
        const float sc_b = gamma[o_b] * rsqrtf(var[o_b] + EPS_);
        const float sh_b = beta[o_b] - mean[o_b] * sc_b;
        float rs_a = 0.f, rs_b = 0.f;
#pragma unroll
        for (int tn = 0; tn < 8; tn++) {
            const int n = n0c + n0w + tn * 8 + 2 * tig;
            float2 va, vb;
            va.x = acc[tm][tn][0] * sc_a + sh_a;
            va.y = acc[tm][tn][1] * sc_a + sh_a;
            vb.x = acc[tm][tn][2] * sc_b + sh_b;
            vb.y = acc[tm][tn][3] * sc_b + sh_b;
            if (doexp) {
                va.x = __expf(va.x); va.y = __expf(va.y);
                vb.x = __expf(vb.x); vb.y = __expf(vb.y);
                rs_a += va.x + va.y;
                rs_b += vb.x + vb.y;
                va.x = __uint_as_float(tf32c(va.x));
                va.y = __uint_as_float(tf32c(va.y));
                vb.x = __uint_as_float(tf32c(vb.x));
                vb.y = __uint_as_float(tf32c(vb.y));
            }
            *(float2*)&Ob[(size_t)o_a * N_ + n] = va;
            *(float2*)&Ob[(size_t)o_b * N_ + n] = vb;
        }
        if (doexp) {
            rs_a += __shfl_xor_sync(0xffffffffu, rs_a, 1);
            rs_a += __shfl_xor_sync(0xffffffffu, rs_a, 2);
            rs_b += __shfl_xor_sync(0xffffffffu, rs_b, 1);
            rs_b += __shfl_xor_sync(0xffffffffu, rs_b, 2);
            if (tig == 0) {
                atomicAdd(&ssum[b * C_ + o_a], rs_a);
                atomicAdd(&ssum[b * C_ + o_b], rs_b);
            }
        }
    }
}

// ---------------------------------------------------------------------------
__global__ __launch_bounds__(256)
void round_w(const float* __restrict__ w)
{
    const int i = blockIdx.x * 256 + threadIdx.x;
    g_wr[i] = __uint_as_float(tf32c(w[i]));
}

// ---------------------------------------------------------------------------
// ctx split-N with fused k-softmax (atomic reduce into zeroed g_ctx)
// ---------------------------------------------------------------------------
__global__ __launch_bounds__(256)
void ctx_kernel()
{
    const int h = blockIdx.x;
    const int b = blockIdx.y;
    const int n0b = blockIdx.z * 256;
    const float* kp = g_qkv + (size_t)b * O3_ * N_ + (size_t)(C_ + h * HD_) * N_;
    const float* vp = g_qkv + (size_t)b * O3_ * N_ + (size_t)(2 * C_ + h * HD_) * N_;

    __shared__ float ks[128][33];
    __shared__ float vs[128][33];

    const int t = threadIdx.x;
    const int i = t >> 4;
    const int j = t & 15;
    float a00 = 0.f, a01 = 0.f, a10 = 0.f, a11 = 0.f;

    for (int cchunk = 0; cchunk < 2; cchunk++) {
        const int n0 = n0b + cchunk * 128;
#pragma unroll
        for (int s = 0; s < 16; s++) {
            const int l = t + s * 256;
            const int d = l >> 7, nn = l & 127;
            ks[nn][d] = kp[(size_t)d * N_ + n0 + nn];
            vs[nn][d] = vp[(size_t)d * N_ + n0 + nn];
        }
        __syncthreads();

        if (t < 128) {
            float m = -CUDART_INF_F;
#pragma unroll
            for (int d = 0; d < HD_; d++) m = fmaxf(m, ks[t][d]);
            float s = 0.f;
#pragma unroll
            for (int d = 0; d < HD_; d++) { float e = __expf(ks[t][d] - m); ks[t][d] = e; s += e; }
            const float inv = 1.f / s;
#pragma unroll
            for (int d = 0; d < HD_; d++) ks[t][d] *= inv;
        }
        __syncthreads();

#pragma unroll 8
        for (int kk = 0; kk < 128; kk++) {
            const float k0 = ks[kk][2 * i], k1 = ks[kk][2 * i + 1];
            const float v0 = vs[kk][2 * j], v1 = vs[kk][2 * j + 1];
            a00 += k0 * v0; a01 += k0 * v1;
            a10 += k1 * v0; a11 += k1 * v1;
        }
        __syncthreads();
    }

    float* cp = g_ctx + (size_t)((b * HEADS_ + h) * HD_) * HD_;
    atomicAdd(&cp[(2 * i + 0) * HD_ + 2 * j + 0], a00);
    atomicAdd(&cp[(2 * i + 0) * HD_ + 2 * j + 1], a01);
    atomicAdd(&cp[(2 * i + 1) * HD_ + 2 * j + 0], a10);
    atomicAdd(&cp[(2 * i + 1) * HD_ + 2 * j + 1], a11);
}

// ---------------------------------------------------------------------------
// fold: M[b,o,c=h*32+d] = tf32( (1/s_c) * sum_e proj_w[o,h*32+e]*ctx[b,h,d,e] )
// ---------------------------------------------------------------------------
extern __shared__ float fold_sm[];

__global__ __launch_bounds__(256)
void fold_kernel(const float* __restrict__ pw)
{
    const int b  = blockIdx.y;
    const int o0 = blockIdx.x * 32;
    const int t  = threadIdx.x;

    float* ctxT = fold_sm;                 // [h][e][d] padded: 8*32*33
    float* pws  = fold_sm + 8 * 32 * 33;   // [32][256]

    const float* cb = g_ctx + (size_t)b * HEADS_ * HD_ * HD_;
#pragma unroll
    for (int s = 0; s < 32; s++) {
        const int idx = t + s * 256;
        const int h = idx >> 10;
        const int d = (idx >> 5) & 31;
        const int e = idx & 31;
        ctxT[(h * 32 + e) * 33 + d] = cb[idx];
    }
#pragma unroll
    for (int oi = 0; oi < 32; oi++)
        pws[oi * 256 + t] = pw[(size_t)(o0 + oi) * C_ + t];
    __syncthreads();

    const int h = t >> 5, d = t & 31;
    const float invs = 1.f / g_ssum[b * C_ + t];
    const float* ct = &ctxT[h * 32 * 33 + d];
    float* Mb = g_M + ((size_t)b * C_ + o0) * C_;

#pragma unroll 4
    for (int oi = 0; oi < 32; oi++) {
        const float* pr = &pws[oi * 256 + h * HD_];
        float s = 0.f;
#pragma unroll
        for (int e = 0; e < HD_; e++)
            s += pr[e] * ct[e * 33];
        Mb[(size_t)oi * C_ + t] = __uint_as_float(tf32c(s * invs));
    }
}

// ---------------------------------------------------------------------------
extern "C" void kernel_launch(void* const* d_in, const int* in_sizes, int n_in,
                              void* d_out, int out_size)
{
    const float* x          = (const float*)d_in[0];
    const float* qkv_w      = (const float*)d_in[1];
    const float* qkv_gamma  = (const float*)d_in[2];
    const float* qkv_beta   = (const float*)d_in[3];
    const float* qkv_mean   = (const float*)d_in[4];
    const float* qkv_var    = (const float*)d_in[5];
    const float* proj_w     = (const float*)d_in[6];
    const float* proj_gamma = (const float*)d_in[7];
    const float* proj_beta  = (const float*)d_in[8];
    const float* proj_mean  = (const float*)d_in[9];
    const float* proj_var   = (const float*)d_in[10];
    float* out = (float*)d_out;

    void* p;
    cudaGetSymbolAddress(&p, g_qkv);  float* qkv = (float*)p;
    cudaGetSymbolAddress(&p, g_M);    float* Mm = (float*)p;
    cudaGetSymbolAddress(&p, g_ctx);  void* ctxp = p;
    cudaGetSymbolAddress(&p, g_ssum); float* ssum = (float*)p;
    cudaGetSymbolAddress(&p, g_wr);   float* wr = (float*)p;

    const int FOLD_SM = (8 * 32 * 33 + 32 * 256) * sizeof(float);
    static int cfg = 0;
    if (!cfg) {
        cudaFuncSetAttribute(fold_kernel, cudaFuncAttributeMaxDynamicSharedMemorySize, FOLD_SM);
        cudaFuncSetAttribute(gemm_tc_bn, cudaFuncAttributeMaxDynamicSharedMemorySize, GSMEM);
        cfg = 1;
    }

    cudaMemsetAsync(ctxp, 0, sizeof(float) * B_ * HEADS_ * HD_ * HD_);
    cudaMemsetAsync(ssum, 0, sizeof(float) * B_ * C_);
    round_w<<<O3_ * C_ / 256, 256>>>(qkv_w);

    // 1) QKV GEMM + BN; A pre-rounded; q exp'd (tf32-rounded) + ssum
    gemm_tc_bn<<<dim3(N_ / 128, O3_ / 128, B_), 256, GSMEM>>>(
        wr, 0, x, (long)C_ * N_, qkv, (long)O3_ * N_,
        qkv_gamma, qkv_beta, qkv_mean, qkv_var, 1, ssum);

    // 2) ctx = softmax_d(k) @ v^T
    ctx_kernel<<<dim3(HEADS_, B_, 16), 256>>>();

    // 3) fold proj_w with ctx, col-scaled 1/s_c, tf32-rounded
    fold_kernel<<<dim3(8, B_), 256, FOLD_SM>>>(proj_w);

    // 4) out = M @ exp_q + proj BN
    gemm_tc_bn<<<dim3(N_ / 128, C_ / 128, B_), 256, GSMEM>>>(
        Mm, (long)C_ * C_, qkv, (long)O3_ * N_, out, (long)C_ * N_,
        proj_gamma, proj_beta, proj_mean, proj_var, 0, ssum);
}

// round 13
// speedup vs baseline: 1.2362x; 1.2362x over previous
#include <cuda_runtime.h>
#include <cstdint>
#include <math_constants.h>

#define B_   16
#define C_   256
#define N_   4096
#define O3_  768
#define HEADS_ 8
#define HD_  32
#define EPS_ 1e-5f

__device__ float g_qkv[(size_t)B_ * O3_ * N_];   // q channels hold tf32-rounded exp(BN(q))
__device__ float g_ctx[(size_t)B_ * HEADS_ * HD_ * HD_];
__device__ float g_M[(size_t)B_ * C_ * C_];      // tf32-rounded, fragment-permuted cols
__device__ float g_ssum[(size_t)B_ * C_];        // s_c = sum_n exp(q[c,n])
__device__ float g_wr[(size_t)O3_ * C_];         // tf32-rounded, fragment-permuted qkv_w

// fragment-major permutation within each 16-k group:
// k = 16*kq + 8*b3 + 4*b2 + tig  ->  pos = 16*kq + 4*tig + 2*b3 + b2
__device__ __forceinline__ int permk16(int k) {
    const int tig = k & 3, b2 = (k >> 2) & 1, b3 = (k >> 3) & 1;
    return (k & ~15) | (tig << 2) | (b3 << 1) | b2;
}

__device__ __forceinline__ uint32_t smem_u32(const void* p) {
    uint32_t a;
    asm("{ .reg .u64 t; cvta.to.shared.u64 t, %1; cvt.u32.u64 %0, t; }"
        : "=r"(a) : "l"(p));
    return a;
}

__device__ __forceinline__ uint32_t tf32c(float f) {
    uint32_t u;
    asm("cvt.rna.tf32.f32 %0, %1;" : "=r"(u) : "f"(f));
    return u;
}

__device__ __forceinline__ void cp16(uint32_t dst, const void* src) {
    asm volatile("cp.async.cg.shared.global [%0], [%1], 16;" :: "r"(dst), "l"(src));
}
#define CP_COMMIT() asm volatile("cp.async.commit_group;" ::: "memory")
#define CP_WAIT0()  asm volatile("cp.async.wait_group 0;" ::: "memory")

__device__ __forceinline__ void mma_tf32(float* c, uint32_t a0, uint32_t a1,
                                         uint32_t a2, uint32_t a3,
                                         uint32_t b0, uint32_t b1) {
    asm volatile(
        "mma.sync.aligned.m16n8k8.row.col.f32.tf32.tf32.f32 "
        "{%0,%1,%2,%3}, {%4,%5,%6,%7}, {%8,%9}, {%0,%1,%2,%3};"
        : "+f"(c[0]), "+f"(c[1]), "+f"(c[2]), "+f"(c[3])
        : "r"(a0), "r"(a1), "r"(a2), "r"(a3), "r"(b0), "r"(b1));
}

#define KT_   32
#define APAD  48      // 48 mod 32 == 16: LDS.128 banks (16*gid + 4*tig) are
                      // disjoint within each 8-lane phase
#define BPAD  136     // floats per B row (128 + 8 pad)
#define ABUF  (128 * APAD)   // 6144 floats
#define BBUF  (KT_ * BPAD)   // 4352 floats
#define GSMEM ((2 * ABUF + 2 * BBUF) * 4)   // 83968 bytes

extern __shared__ float gem_sm[];

// ---------------------------------------------------------------------------
// tf32 tensor-core GEMM, 128x128 tile, K=256, k-tile 32, 2-stage cp.async.
// A is fragment-permuted (permk16) in gmem -> A fragments via LDS.128.
// C[o,n] = BN( sum_k A[o,k] * Bm[k,n] )  per batch (blockIdx.z).
// ---------------------------------------------------------------------------
__global__ __launch_bounds__(256, 2)
void gemm_tc_bn(const float* __restrict__ A, long aStride,
                const float* __restrict__ Bm, long bStride,
                float* __restrict__ Out, long oStride,
                const float* __restrict__ gamma, const float* __restrict__ beta,
                const float* __restrict__ mean,  const float* __restrict__ var,
                int expq, float* __restrict__ ssum)
{
    const int b   = blockIdx.z;
    const int n0c = blockIdx.x * 128;
    const int o0c = blockIdx.y * 128;
    const float* Ab = A  + (size_t)b * aStride;
    const float* Bb = Bm + (size_t)b * bStride;
    float*       Ob = Out + (size_t)b * oStride;

    float* Asm = gem_sm;
    float* Bsm = gem_sm + 2 * ABUF;

    const int t    = threadIdx.x;
    const int wid  = t >> 5;
    const int lane = t & 31;
    const int gid  = lane >> 2;
    const int tig  = lane & 3;
    const int m0   = (wid & 3) * 32;
    const int n0w  = (wid >> 2) * 64;

    const uint32_t smA = smem_u32(Asm);
    const uint32_t smB = smem_u32(Bsm);

    float acc[2][8][4];
#pragma unroll
    for (int tm = 0; tm < 2; tm++)
#pragma unroll
        for (int tn = 0; tn < 8; tn++)
#pragma unroll
            for (int q = 0; q < 4; q++) acc[tm][tn][q] = 0.f;

    // ---- prefetch tile 0 ----
#pragma unroll
    for (int r = 0; r < 4; r++) {
        const int c = t + r * 256;
        const int o = c >> 3, kp = (c & 7) * 4;
        cp16(smA + (uint32_t)(o * APAD + kp) * 4,
             Ab + (size_t)(o0c + o) * 256 + kp);
    }
#pragma unroll
    for (int r = 0; r < 4; r++) {
        const int c = t + r * 256;
        const int k = c >> 5, np = (c & 31) * 4;
        cp16(smB + (uint32_t)(k * BPAD + np) * 4,
             Bb + (size_t)k * N_ + n0c + np);
    }
    CP_COMMIT();

    for (int kt = 0; kt < 8; kt++) {
        CP_WAIT0();
        __syncthreads();

        if (kt < 7) {
            const int k0 = (kt + 1) * KT_;
            const uint32_t bufo = (uint32_t)((kt + 1) & 1);
            const uint32_t dA = smA + bufo * (ABUF * 4);
            const uint32_t dB = smB + bufo * (BBUF * 4);
#pragma unroll
            for (int r = 0; r < 4; r++) {
                const int c = t + r * 256;
                const int o = c >> 3, kp = (c & 7) * 4;
                cp16(dA + (uint32_t)(o * APAD + kp) * 4,
                     Ab + (size_t)(o0c + o) * 256 + k0 + kp);
            }
#pragma unroll
            for (int r = 0; r < 4; r++) {
                const int c = t + r * 256;
                const int k = c >> 5, np = (c & 31) * 4;
                cp16(dB + (uint32_t)(k * BPAD + np) * 4,
                     Bb + (size_t)(k0 + k) * N_ + n0c + np);
            }
            CP_COMMIT();
        }

        const float* As2 = Asm + (kt & 1) * ABUF;
        const float* Bs2 = Bsm + (kt & 1) * BBUF;

#pragma unroll
        for (int c2 = 0; c2 < 2; c2++) {
            // one LDS.128 per row covers the A fragments of 2 ks-steps:
            // (x,y,z,w) = k = 16*c2 + {tig, tig+4, tig+8, tig+12}
            float4 av[4];
#pragma unroll
            for (int tm = 0; tm < 2; tm++) {
                const int oa = (m0 + tm * 16 + gid) * APAD + c2 * 16 + tig * 4;
                av[2 * tm]     = *(const float4*)&As2[oa];
                av[2 * tm + 1] = *(const float4*)&As2[oa + 8 * APAD];
            }
#pragma unroll
            for (int h = 0; h < 2; h++) {
                const int kb = (c2 * 2 + h) * 8;
                uint32_t bf[8][2];
#pragma unroll
                for (int tn = 0; tn < 8; tn++) {
                    bf[tn][0] = __float_as_uint(Bs2[(kb + tig) * BPAD + n0w + tn * 8 + gid]);
                    bf[tn][1] = __float_as_uint(Bs2[(kb + tig + 4) * BPAD + n0w + tn * 8 + gid]);
                }
#pragma unroll
                for (int tm = 0; tm < 2; tm++) {
                    const uint32_t a0 = __float_as_uint(h ? av[2 * tm].z     : av[2 * tm].x);
                    const uint32_t a2 = __float_as_uint(h ? av[2 * tm].w     : av[2 * tm].y);
                    const uint32_t a1 = __float_as_uint(h ? av[2 * tm + 1].z : av[2 * tm + 1].x);
                    const uint32_t a3 = __float_as_uint(h ? av[2 * tm + 1].w : av[2 * tm + 1].y);
#pragma unroll
                    for (int tn = 0; tn < 8; tn++)
                        mma_tf32(acc[tm][tn], a0, a1, a2, a3, bf[tn][0], bf[tn][1]);
                }
            }
        }
    }

    const int doexp = expq && (o0c < 256);

#pragma unroll
    for (int tm = 0; tm < 2; tm++) {
        const int o_a = o0c + m0 + tm * 16 + gid;
        const int o_b = o_a + 8;
        const float sc_a = gamma[o_a] * rsqrtf(var[o_a] + EPS_);
        const float sh_a = beta[o_a] - mean[o_a] * sc_a;
        const float sc_b = gamma[o_b] * rsqrtf(var[o_b] + EPS_);
        const float sh_b = beta[o_b] - mean[o_b] * sc_b;
        float rs_a = 0.f, rs_b = 0.f;
#pragma unroll
        for (int tn = 0; tn < 8; tn++) {
            const int n = n0c + n0w + tn * 8 + 2 * tig;
            float2 va, vb;
            va.x = acc[tm][tn][0] * sc_a + sh_a;
            va.y = acc[tm][tn][1] * sc_a + sh_a;
            vb.x = acc[tm][tn][2] * sc_b + sh_b;
            vb.y = acc[tm][tn][3] * sc_b + sh_b;
            if (doexp) {
                va.x = __expf(va.x); va.y = __expf(va.y);
                vb.x = __expf(vb.x); vb.y = __expf(vb.y);
                rs_a += va.x + va.y;
                rs_b += vb.x + vb.y;
                va.x = __uint_as_float(tf32c(va.x));
                va.y = __uint_as_float(tf32c(va.y));
                vb.x = __uint_as_float(tf32c(vb.x));
                vb.y = __uint_as_float(tf32c(vb.y));
            }
            *(float2*)&Ob[(size_t)o_a * N_ + n] = va;
            *(float2*)&Ob[(size_t)o_b * N_ + n] = vb;
        }
        if (doexp) {
            rs_a += __shfl_xor_sync(0xffffffffu, rs_a, 1);
            rs_a += __shfl_xor_sync(0xffffffffu, rs_a, 2);
            rs_b += __shfl_xor_sync(0xffffffffu, rs_b, 1);
            rs_b += __shfl_xor_sync(0xffffffffu, rs_b, 2);
            if (tig == 0) {
                atomicAdd(&ssum[b * C_ + o_a], rs_a);
                atomicAdd(&ssum[b * C_ + o_b], rs_b);
            }
        }
    }
}

// ---------------------------------------------------------------------------
// Pre-round qkv_w to tf32, store fragment-permuted
// ---------------------------------------------------------------------------
__global__ __launch_bounds__(256)
void round_w(const float* __restrict__ w)
{
    const int i = blockIdx.x * 256 + threadIdx.x;
    const int o = i >> 8, c = i & 255;
    g_wr[(size_t)o * C_ + permk16(c)] = __uint_as_float(tf32c(w[i]));
}

// ---------------------------------------------------------------------------
// ctx split-N with fused k-softmax (atomic reduce into zeroed g_ctx)
// ---------------------------------------------------------------------------
__global__ __launch_bounds__(256)
void ctx_kernel()
{
    const int h = blockIdx.x;
    const int b = blockIdx.y;
    const int n0b = blockIdx.z * 256;
    const float* kp = g_qkv + (size_t)b * O3_ * N_ + (size_t)(C_ + h * HD_) * N_;
    const float* vp = g_qkv + (size_t)b * O3_ * N_ + (size_t)(2 * C_ + h * HD_) * N_;

    __shared__ float ks[128][33];
    __shared__ float vs[128][33];

    const int t = threadIdx.x;
    const int i = t >> 4;
    const int j = t & 15;
    float a00 = 0.f, a01 = 0.f, a10 = 0.f, a11 = 0.f;

    for (int cchunk = 0; cchunk < 2; cchunk++) {
        const int n0 = n0b + cchunk * 128;
#pragma unroll
        for (int s = 0; s < 16; s++) {
            const int l = t + s * 256;
            const int d = l >> 7, nn = l & 127;
            ks[nn][d] = kp[(size_t)d * N_ + n0 + nn];
            vs[nn][d] = vp[(size_t)d * N_ + n0 + nn];
        }
        __syncthreads();

        if (t < 128) {
            float m = -CUDART_INF_F;
#pragma unroll
            for (int d = 0; d < HD_; d++) m = fmaxf(m, ks[t][d]);
            float s = 0.f;
#pragma unroll
            for (int d = 0; d < HD_; d++) { float e = __expf(ks[t][d] - m); ks[t][d] = e; s += e; }
            const float inv = 1.f / s;
#pragma unroll
            for (int d = 0; d < HD_; d++) ks[t][d] *= inv;
        }
        __syncthreads();

#pragma unroll 8
        for (int kk = 0; kk < 128; kk++) {
            const float k0 = ks[kk][2 * i], k1 = ks[kk][2 * i + 1];
            const float v0 = vs[kk][2 * j], v1 = vs[kk][2 * j + 1];
            a00 += k0 * v0; a01 += k0 * v1;
            a10 += k1 * v0; a11 += k1 * v1;
        }
        __syncthreads();
    }

    float* cp = g_ctx + (size_t)((b * HEADS_ + h) * HD_) * HD_;
    atomicAdd(&cp[(2 * i + 0) * HD_ + 2 * j + 0], a00);
    atomicAdd(&cp[(2 * i + 0) * HD_ + 2 * j + 1], a01);
    atomicAdd(&cp[(2 * i + 1) * HD_ + 2 * j + 0], a10);
    atomicAdd(&cp[(2 * i + 1) * HD_ + 2 * j + 1], a11);
}

// ---------------------------------------------------------------------------
// fold: M[b,o,permk16(c)] = tf32( (1/s_c)*sum_e proj_w[o,h*32+e]*ctx[b,h,d,e] )
// ---------------------------------------------------------------------------
extern __shared__ float fold_sm[];

__global__ __launch_bounds__(256)
void fold_kernel(const float* __restrict__ pw)
{
    const int b  = blockIdx.y;
    const int o0 = blockIdx.x * 32;
    const int t  = threadIdx.x;

    float* ctxT = fold_sm;                 // [h][e][d] padded: 8*32*33
    float* pws  = fold_sm + 8 * 32 * 33;   // [32][256]

    const float* cb = g_ctx + (size_t)b * HEADS_ * HD_ * HD_;
#pragma unroll
    for (int s = 0; s < 32; s++) {
        const int idx = t + s * 256;
        const int h = idx >> 10;
        const int d = (idx >> 5) & 31;
        const int e = idx & 31;
        ctxT[(h * 32 + e) * 33 + d] = cb[idx];
    }
#pragma unroll
    for (int oi = 0; oi < 32; oi++)
        pws[oi * 256 + t] = pw[(size_t)(o0 + oi) * C_ + t];
    __syncthreads();

    const int h = t >> 5, d = t & 31;
    const float invs = 1.f / g_ssum[b * C_ + t];
    const float* ct = &ctxT[h * 32 * 33 + d];
    float* Mb = g_M + ((size_t)b * C_ + o0) * C_;
    const int tp = permk16(t);

#pragma unroll 4
    for (int oi = 0; oi < 32; oi++) {
        const float* pr = &pws[oi * 256 + h * HD_];
        float s = 0.f;
#pragma unroll
        for (int e = 0; e < HD_; e++)
            s += pr[e] * ct[e * 33];
        Mb[(size_t)oi * C_ + tp] = __uint_as_float(tf32c(s * invs));
    }
}

// ---------------------------------------------------------------------------
extern "C" void kernel_launch(void* const* d_in, const int* in_sizes, int n_in,
                              void* d_out, int out_size)
{
    const float* x          = (const float*)d_in[0];
    const float* qkv_w      = (const float*)d_in[1];
    const float* qkv_gamma  = (const float*)d_in[2];
    const float* qkv_beta   = (const float*)d_in[3];
    const float* qkv_mean   = (const float*)d_in[4];
    const float* qkv_var    = (const float*)d_in[5];
    const float* proj_w     = (const float*)d_in[6];
    const float* proj_gamma = (const float*)d_in[7];
    const float* proj_beta  = (const float*)d_in[8];
    const float* proj_mean  = (const float*)d_in[9];
    const float* proj_var   = (const float*)d_in[10];
    float* out = (float*)d_out;

    void* p;
    cudaGetSymbolAddress(&p, g_qkv);  float* qkv = (float*)p;
    cudaGetSymbolAddress(&p, g_M);    float* Mm = (float*)p;
    cudaGetSymbolAddress(&p, g_ctx);  void* ctxp = p;
    cudaGetSymbolAddress(&p, g_ssum); float* ssum = (float*)p;
    cudaGetSymbolAddress(&p, g_wr);   float* wr = (float*)p;

    const int FOLD_SM = (8 * 32 * 33 + 32 * 256) * sizeof(float);
    static int cfg = 0;
    if (!cfg) {
        cudaFuncSetAttribute(fold_kernel, cudaFuncAttributeMaxDynamicSharedMemorySize, FOLD_SM);
        cudaFuncSetAttribute(gemm_tc_bn, cudaFuncAttributeMaxDynamicSharedMemorySize, GSMEM);
        cfg = 1;
    }

    cudaMemsetAsync(ctxp, 0, sizeof(float) * B_ * HEADS_ * HD_ * HD_);
    cudaMemsetAsync(ssum, 0, sizeof(float) * B_ * C_);
    round_w<<<O3_ * C_ / 256, 256>>>(qkv_w);

    // 1) QKV GEMM + BN; A pre-rounded fragment-permuted; q exp'd + ssum
    gemm_tc_bn<<<dim3(N_ / 128, O3_ / 128, B_), 256, GSMEM>>>(
        wr, 0, x, (long)C_ * N_, qkv, (long)O3_ * N_,
        qkv_gamma, qkv_beta, qkv_mean, qkv_var, 1, ssum);

    // 2) ctx = softmax_d(k) @ v^T
    ctx_kernel<<<dim3(HEADS_, B_, 16), 256>>>();

    // 3) fold proj_w with ctx, col-scaled 1/s_c, tf32-rounded, frag-permuted
    fold_kernel<<<dim3(8, B_), 256, FOLD_SM>>>(proj_w);

    // 4) out = M @ exp_q + proj BN
    gemm_tc_bn<<<dim3(N_ / 128, C_ / 128, B_), 256, GSMEM>>>(
        Mm, (long)C_ * C_, qkv, (long)O3_ * N_, out, (long)C_ * N_,
        proj_gamma, proj_beta, proj_mean, proj_var, 0, ssum);
}

// round 14
// speedup vs baseline: 1.3309x; 1.0766x over previous
#include <cuda_runtime.h>
#include <cstdint>
#include <math_constants.h>

#define B_   16
#define C_   256
#define N_   4096
#define O3_  768
#define HEADS_ 8
#define HD_  32
#define EPS_ 1e-5f

__device__ float g_qkv[(size_t)B_ * O3_ * N_];   // q channels hold tf32-rounded exp(BN(q))
__device__ float g_ctx[(size_t)B_ * HEADS_ * HD_ * HD_];
__device__ float g_M[(size_t)B_ * C_ * C_];      // tf32-rounded proj_w @ ctx / s_c
__device__ float g_ssum[(size_t)B_ * C_];        // s_c = sum_n exp(q[c,n])
__device__ float g_wr[(size_t)O3_ * C_];         // tf32-rounded qkv_w

__device__ __forceinline__ uint32_t smem_u32(const void* p) {
    uint32_t a;
    asm("{ .reg .u64 t; cvta.to.shared.u64 t, %1; cvt.u32.u64 %0, t; }"
        : "=r"(a) : "l"(p));
    return a;
}

__device__ __forceinline__ uint32_t tf32c(float f) {
    uint32_t u;
    asm("cvt.rna.tf32.f32 %0, %1;" : "=r"(u) : "f"(f));
    return u;
}

__device__ __forceinline__ void cp16(uint32_t dst, const void* src) {
    asm volatile("cp.async.cg.shared.global [%0], [%1], 16;" :: "r"(dst), "l"(src));
}
#define CP_COMMIT() asm volatile("cp.async.commit_group;" ::: "memory")
#define CP_WAIT0()  asm volatile("cp.async.wait_group 0;" ::: "memory")

__device__ __forceinline__ void mma_tf32(float* c, uint32_t a0, uint32_t a1,
                                         uint32_t a2, uint32_t a3,
                                         uint32_t b0, uint32_t b1) {
    asm volatile(
        "mma.sync.aligned.m16n8k8.row.col.f32.tf32.tf32.f32 "
        "{%0,%1,%2,%3}, {%4,%5,%6,%7}, {%8,%9}, {%0,%1,%2,%3};"
        : "+f"(c[0]), "+f"(c[1]), "+f"(c[2]), "+f"(c[3])
        : "r"(a0), "r"(a1), "r"(a2), "r"(a3), "r"(b0), "r"(b1));
}

#define KT_   32
#define APAD  36      // floats per A row (32 + 4 pad)
#define BPAD  136     // floats per B row (128 + 8 pad)
#define ABUF  (128 * APAD)
#define BBUF  (KT_ * BPAD)
#define GSMEM ((2 * ABUF + 2 * BBUF) * 4)   // 71680 bytes

extern __shared__ float gem_sm[];

// ---------------------------------------------------------------------------
// tf32 tensor-core GEMM, 128x128 tile, K=256, k-tile 32, 2-stage cp.async.
// C[o,n] = BN( sum_k A[o,k] * Bm[k,n] )  per batch (blockIdx.z).
// expq: q-channel tiles store tf32-rounded exp(BN(.)) + ssum atomics.
// ---------------------------------------------------------------------------
__global__ __launch_bounds__(256, 2)
void gemm_tc_bn(const float* __restrict__ A, long aStride,
                const float* __restrict__ Bm, long bStride,
                float* __restrict__ Out, long oStride,
                const float* __restrict__ gamma, const float* __restrict__ beta,
                const float* __restrict__ mean,  const float* __restrict__ var,
                int expq, float* __restrict__ ssum)
{
    const int b   = blockIdx.z;
    const int n0c = blockIdx.x * 128;
    const int o0c = blockIdx.y * 128;
    const float* Ab = A  + (size_t)b * aStride;
    const float* Bb = Bm + (size_t)b * bStride;
    float*       Ob = Out + (size_t)b * oStride;

    float* Asm = gem_sm;
    float* Bsm = gem_sm + 2 * ABUF;

    const int t    = threadIdx.x;
    const int wid  = t >> 5;
    const int lane = t & 31;
    const int gid  = lane >> 2;
    const int tig  = lane & 3;
    const int m0   = (wid & 3) * 32;
    const int n0w  = (wid >> 2) * 64;

    const uint32_t smA = smem_u32(Asm);
    const uint32_t smB = smem_u32(Bsm);

    float acc[2][8][4];
#pragma unroll
    for (int tm = 0; tm < 2; tm++)
#pragma unroll
        for (int tn = 0; tn < 8; tn++)
#pragma unroll
            for (int q = 0; q < 4; q++) acc[tm][tn][q] = 0.f;

    // ---- prefetch tile 0 ----
#pragma unroll
    for (int r = 0; r < 4; r++) {
        const int c = t + r * 256;
        const int o = c >> 3, kp = (c & 7) * 4;
        cp16(smA + (uint32_t)(o * APAD + kp) * 4,
             Ab + (size_t)(o0c + o) * 256 + kp);
    }
#pragma unroll
    for (int r = 0; r < 4; r++) {
        const int c = t + r * 256;
        const int k = c >> 5, np = (c & 31) * 4;
        cp16(smB + (uint32_t)(k * BPAD + np) * 4,
             Bb + (size_t)k * N_ + n0c + np);
    }
    CP_COMMIT();

#pragma unroll 2
    for (int kt = 0; kt < 8; kt++) {
        CP_WAIT0();
        __syncthreads();

        if (kt < 7) {
            const int k0 = (kt + 1) * KT_;
            const uint32_t bufo = (uint32_t)((kt + 1) & 1);
            const uint32_t dA = smA + bufo * (ABUF * 4);
            const uint32_t dB = smB + bufo * (BBUF * 4);
#pragma unroll
            for (int r = 0; r < 4; r++) {
                const int c = t + r * 256;
                const int o = c >> 3, kp = (c & 7) * 4;
                cp16(dA + (uint32_t)(o * APAD + kp) * 4,
                     Ab + (size_t)(o0c + o) * 256 + k0 + kp);
            }
#pragma unroll
            for (int r = 0; r < 4; r++) {
                const int c = t + r * 256;
                const int k = c >> 5, np = (c & 31) * 4;
                cp16(dB + (uint32_t)(k * BPAD + np) * 4,
                     Bb + (size_t)(k0 + k) * N_ + n0c + np);
            }
            CP_COMMIT();
        }

        const float* As2 = Asm + (kt & 1) * ABUF;
        const float* Bs2 = Bsm + (kt & 1) * BBUF;

#pragma unroll
        for (int ks = 0; ks < 4; ks++) {
            const int kb = ks * 8;
            uint32_t bf[8][2];
#pragma unroll
            for (int tn = 0; tn < 8; tn++) {
                bf[tn][0] = __float_as_uint(Bs2[(kb + tig) * BPAD + n0w + tn * 8 + gid]);
                bf[tn][1] = __float_as_uint(Bs2[(kb + tig + 4) * BPAD + n0w + tn * 8 + gid]);
            }
#pragma unroll
            for (int tm = 0; tm < 2; tm++) {
                const int oa = (m0 + tm * 16 + gid) * APAD;
                const int ob = oa + 8 * APAD;
                const uint32_t a0 = __float_as_uint(As2[oa + kb + tig]);
                const uint32_t a1 = __float_as_uint(As2[ob + kb + tig]);
                const uint32_t a2 = __float_as_uint(As2[oa + kb + tig + 4]);
                const uint32_t a3 = __float_as_uint(As2[ob + kb + tig + 4]);
#pragma unroll
                for (int tn = 0; tn < 8; tn++)
                    mma_tf32(acc[tm][tn], a0, a1, a2, a3, bf[tn][0], bf[tn][1]);
            }
        }
    }

    const int doexp = expq && (o0c < 256);

#pragma unroll
    for (int tm = 0; tm < 2; tm++) {
        const int o_a = o0c + m0 + tm * 16 + gid;
        const int o_b = o_a + 8;
        const float sc_a = gamma[o_a] * rsqrtf(var[o_a] + EPS_);
        const float sh_a = beta[o_a] - mean[o_a] * sc_a;
        const float sc_b = gamma[o_b] * rsqrtf(var[o_b] + EPS_);
        const float sh_b = beta[o_b] - mean[o_b] * sc_b;
        float rs_a = 0.f, rs_b = 0.f;
#pragma unroll
        for (int tn = 0; tn < 8; tn++) {
            const int n = n0c + n0w + tn * 8 + 2 * tig;
            float2 va, vb;
            va.x = acc[tm][tn][0] * sc_a + sh_a;
            va.y = acc[tm][tn][1] * sc_a + sh_a;
            vb.x = acc[tm][tn][2] * sc_b + sh_b;
            vb.y = acc[tm][tn][3] * sc_b + sh_b;
            if (doexp) {
                va.x = __expf(va.x); va.y = __expf(va.y);
                vb.x = __expf(vb.x); vb.y = __expf(vb.y);
                rs_a += va.x + va.y;
                rs_b += vb.x + vb.y;
                va.x = __uint_as_float(tf32c(va.x));
                va.y = __uint_as_float(tf32c(va.y));
                vb.x = __uint_as_float(tf32c(vb.x));
                vb.y = __uint_as_float(tf32c(vb.y));
            }
            *(float2*)&Ob[(size_t)o_a * N_ + n] = va;
            *(float2*)&Ob[(size_t)o_b * N_ + n] = vb;
        }
        if (doexp) {
            rs_a += __shfl_xor_sync(0xffffffffu, rs_a, 1);
            rs_a += __shfl_xor_sync(0xffffffffu, rs_a, 2);
            rs_b += __shfl_xor_sync(0xffffffffu, rs_b, 1);
            rs_b += __shfl_xor_sync(0xffffffffu, rs_b, 2);
            if (tig == 0) {
                atomicAdd(&ssum[b * C_ + o_a], rs_a);
                atomicAdd(&ssum[b * C_ + o_b], rs_b);
            }
        }
    }
}

// ---------------------------------------------------------------------------
// Pre-round qkv_w to tf32 + zero ctx/ssum accumulators (replaces 2 memsets;
// stream order guarantees completion before downstream atomics)
// ---------------------------------------------------------------------------
__global__ __launch_bounds__(256)
void round_w(const float* __restrict__ w)
{
    const int i = blockIdx.x * 256 + threadIdx.x;
    g_wr[i] = __uint_as_float(tf32c(w[i]));
    if (i < B_ * HEADS_ * HD_ * HD_) g_ctx[i] = 0.f;
    if (i < B_ * C_) g_ssum[i] = 0.f;
}

// ---------------------------------------------------------------------------
// ctx split-N with fused k-softmax (atomic reduce into zeroed g_ctx)
// ---------------------------------------------------------------------------
__global__ __launch_bounds__(256)
void ctx_kernel()
{
    const int h = blockIdx.x;
    const int b = blockIdx.y;
    const int n0b = blockIdx.z * 256;
    const float* kp = g_qkv + (size_t)b * O3_ * N_ + (size_t)(C_ + h * HD_) * N_;
    const float* vp = g_qkv + (size_t)b * O3_ * N_ + (size_t)(2 * C_ + h * HD_) * N_;

    __shared__ float ks[128][33];
    __shared__ float vs[128][33];

    const int t = threadIdx.x;
    const int i = t >> 4;
    const int j = t & 15;
    float a00 = 0.f, a01 = 0.f, a10 = 0.f, a11 = 0.f;

    for (int cchunk = 0; cchunk < 2; cchunk++) {
        const int n0 = n0b + cchunk * 128;
#pragma unroll
        for (int s = 0; s < 16; s++) {
            const int l = t + s * 256;
            const int d = l >> 7, nn = l & 127;
            ks[nn][d] = kp[(size_t)d * N_ + n0 + nn];
            vs[nn][d] = vp[(size_t)d * N_ + n0 + nn];
        }
        __syncthreads();

        if (t < 128) {
            float m = -CUDART_INF_F;
#pragma unroll
            for (int d = 0; d < HD_; d++) m = fmaxf(m, ks[t][d]);
            float s = 0.f;
#pragma unroll
            for (int d = 0; d < HD_; d++) { float e = __expf(ks[t][d] - m); ks[t][d] = e; s += e; }
            const float inv = 1.f / s;
#pragma unroll
            for (int d = 0; d < HD_; d++) ks[t][d] *= inv;
        }
        __syncthreads();

#pragma unroll 8
        for (int kk = 0; kk < 128; kk++) {
            const float k0 = ks[kk][2 * i], k1 = ks[kk][2 * i + 1];
            const float v0 = vs[kk][2 * j], v1 = vs[kk][2 * j + 1];
            a00 += k0 * v0; a01 += k0 * v1;
            a10 += k1 * v0; a11 += k1 * v1;
        }
        __syncthreads();
    }

    float* cp = g_ctx + (size_t)((b * HEADS_ + h) * HD_) * HD_;
    atomicAdd(&cp[(2 * i + 0) * HD_ + 2 * j + 0], a00);
    atomicAdd(&cp[(2 * i + 0) * HD_ + 2 * j + 1], a01);
    atomicAdd(&cp[(2 * i + 1) * HD_ + 2 * j + 0], a10);
    atomicAdd(&cp[(2 * i + 1) * HD_ + 2 * j + 1], a11);
}

// ---------------------------------------------------------------------------
// fold: M[b,o,c=h*32+d] = tf32( (1/s_c) * sum_e proj_w[o,h*32+e]*ctx[b,h,d,e] )
// ---------------------------------------------------------------------------
extern __shared__ float fold_sm[];

__global__ __launch_bounds__(256)
void fold_kernel(const float* __restrict__ pw)
{
    const int b  = blockIdx.y;
    const int o0 = blockIdx.x * 32;
    const int t  = threadIdx.x;

    float* ctxT = fold_sm;                 // [h][e][d] padded: 8*32*33
    float* pws  = fold_sm + 8 * 32 * 33;   // [32][256]

    const float* cb = g_ctx + (size_t)b * HEADS_ * HD_ * HD_;
#pragma unroll
    for (int s = 0; s < 32; s++) {
        const int idx = t + s * 256;
        const int h = idx >> 10;
        const int d = (idx >> 5) & 31;
        const int e = idx & 31;
        ctxT[(h * 32 + e) * 33 + d] = cb[idx];
    }
#pragma unroll
    for (int oi = 0; oi < 32; oi++)
        pws[oi * 256 + t] = pw[(size_t)(o0 + oi) * C_ + t];
    __syncthreads();

    const int h = t >> 5, d = t & 31;
    const float invs = 1.f / g_ssum[b * C_ + t];
    const float* ct = &ctxT[h * 32 * 33 + d];
    float* Mb = g_M + ((size_t)b * C_ + o0) * C_;

#pragma unroll 4
    for (int oi = 0; oi < 32; oi++) {
        const float* pr = &pws[oi * 256 + h * HD_];
        float s = 0.f;
#pragma unroll
        for (int e = 0; e < HD_; e++)
            s += pr[e] * ct[e * 33];
        Mb[(size_t)oi * C_ + t] = __uint_as_float(tf32c(s * invs));
    }
}

// ---------------------------------------------------------------------------
extern "C" void kernel_launch(void* const* d_in, const int* in_sizes, int n_in,
                              void* d_out, int out_size)
{
    const float* x          = (const float*)d_in[0];
    const float* qkv_w      = (const float*)d_in[1];
    const float* qkv_gamma  = (const float*)d_in[2];
    const float* qkv_beta   = (const float*)d_in[3];
    const float* qkv_mean   = (const float*)d_in[4];
    const float* qkv_var    = (const float*)d_in[5];
    const float* proj_w     = (const float*)d_in[6];
    const float* proj_gamma = (const float*)d_in[7];
    const float* proj_beta  = (const float*)d_in[8];
    const float* proj_mean  = (const float*)d_in[9];
    const float* proj_var   = (const float*)d_in[10];
    float* out = (float*)d_out;

    void* p;
    cudaGetSymbolAddress(&p, g_qkv);  float* qkv = (float*)p;
    cudaGetSymbolAddress(&p, g_M);    float* Mm = (float*)p;
    cudaGetSymbolAddress(&p, g_ssum); float* ssum = (float*)p;
    cudaGetSymbolAddress(&p, g_wr);   float* wr = (float*)p;

    const int FOLD_SM = (8 * 32 * 33 + 32 * 256) * sizeof(float);
    static int cfg = 0;
    if (!cfg) {
        cudaFuncSetAttribute(fold_kernel, cudaFuncAttributeMaxDynamicSharedMemorySize, FOLD_SM);
        cudaFuncSetAttribute(gemm_tc_bn, cudaFuncAttributeMaxDynamicSharedMemorySize, GSMEM);
        cfg = 1;
    }

    // 0) round weights + zero accumulators (fused, replaces 2 memsets)
    round_w<<<O3_ * C_ / 256, 256>>>(qkv_w);

    // 1) QKV GEMM + BN; A pre-rounded; q exp'd (tf32-rounded) + ssum
    gemm_tc_bn<<<dim3(N_ / 128, O3_ / 128, B_), 256, GSMEM>>>(
        wr, 0, x, (long)C_ * N_, qkv, (long)O3_ * N_,
        qkv_gamma, qkv_beta, qkv_mean, qkv_var, 1, ssum);

    // 2) ctx = softmax_d(k) @ v^T
    ctx_kernel<<<dim3(HEADS_, B_, 16), 256>>>();

    // 3) fold proj_w with ctx, col-scaled 1/s_c, tf32-rounded
    fold_kernel<<<dim3(8, B_), 256, FOLD_SM>>>(proj_w);

    // 4) out = M @ exp_q + proj BN
    gemm_tc_bn<<<dim3(N_ / 128, C_ / 128, B_), 256, GSMEM>>>(
        Mm, (long)C_ * C_, qkv, (long)O3_ * N_, out, (long)C_ * N_,
        proj_gamma, proj_beta, proj_mean, proj_var, 0, ssum);
}

// round 15
// speedup vs baseline: 1.3779x; 1.0353x over previous
#include <cuda_runtime.h>
#include <cstdint>
#include <math_constants.h>

#define B_   16
#define C_   256
#define N_   4096
#define O3_  768
#define HEADS_ 8
#define HD_  32
#define EPS_ 1e-5f

__device__ float g_qkv[(size_t)B_ * O3_ * N_];   // q channels hold tf32-rounded exp(BN(q))
__device__ float g_ctx[(size_t)B_ * HEADS_ * HD_ * HD_];
__device__ float g_M[(size_t)B_ * C_ * C_];      // tf32-rounded proj_w @ ctx / s_c
__device__ float g_ssum[(size_t)B_ * C_];        // s_c = sum_n exp(q[c,n])
__device__ float g_wr[(size_t)O3_ * C_];         // tf32-rounded qkv_w

__device__ __forceinline__ uint32_t smem_u32(const void* p) {
    uint32_t a;
    asm("{ .reg .u64 t; cvta.to.shared.u64 t, %1; cvt.u32.u64 %0, t; }"
        : "=r"(a) : "l"(p));
    return a;
}

__device__ __forceinline__ uint32_t tf32c(float f) {
    uint32_t u;
    asm("cvt.rna.tf32.f32 %0, %1;" : "=r"(u) : "f"(f));
    return u;
}

__device__ __forceinline__ void cp16(uint32_t dst, const void* src) {
    asm volatile("cp.async.cg.shared.global [%0], [%1], 16;" :: "r"(dst), "l"(src));
}
#define CP_COMMIT() asm volatile("cp.async.commit_group;" ::: "memory")
#define CP_WAIT0()  asm volatile("cp.async.wait_group 0;" ::: "memory")

__device__ __forceinline__ void mma_tf32(float* c, uint32_t a0, uint32_t a1,
                                         uint32_t a2, uint32_t a3,
                                         uint32_t b0, uint32_t b1) {
    asm volatile(
        "mma.sync.aligned.m16n8k8.row.col.f32.tf32.tf32.f32 "
        "{%0,%1,%2,%3}, {%4,%5,%6,%7}, {%8,%9}, {%0,%1,%2,%3};"
        : "+f"(c[0]), "+f"(c[1]), "+f"(c[2]), "+f"(c[3])
        : "r"(a0), "r"(a1), "r"(a2), "r"(a3), "r"(b0), "r"(b1));
}

#define KT_   32
#define APAD  36      // floats per A row (32 + 4 pad)
#define BPAD  136     // floats per B row (128 + 8 pad)
#define ABUF  (128 * APAD)
#define BBUF  (KT_ * BPAD)
#define GSMEM ((2 * ABUF + 2 * BBUF) * 4)   // 71680 bytes

extern __shared__ float gem_sm[];

// ---------------------------------------------------------------------------
// tf32 tensor-core GEMM, 128x128 CTA tile, 64x64 WARP tile (4 warps, 128 thr),
// K=256, k-tile 32, 2-stage cp.async. LDS/MMA ratio 1.0 (was 1.5).
// C[o,n] = BN( sum_k A[o,k] * Bm[k,n] )  per batch (blockIdx.z).
// expq: q-channel tiles store tf32-rounded exp(BN(.)) + ssum atomics.
// ---------------------------------------------------------------------------
__global__ __launch_bounds__(128)
void gemm_tc_bn(const float* __restrict__ A, long aStride,
                const float* __restrict__ Bm, long bStride,
                float* __restrict__ Out, long oStride,
                const float* __restrict__ gamma, const float* __restrict__ beta,
                const float* __restrict__ mean,  const float* __restrict__ var,
                int expq, float* __restrict__ ssum)
{
    const int b   = blockIdx.z;
    const int n0c = blockIdx.x * 128;
    const int o0c = blockIdx.y * 128;
    const float* Ab = A  + (size_t)b * aStride;
    const float* Bb = Bm + (size_t)b * bStride;
    float*       Ob = Out + (size_t)b * oStride;

    float* Asm = gem_sm;
    float* Bsm = gem_sm + 2 * ABUF;

    const int t    = threadIdx.x;      // 128 threads
    const int wid  = t >> 5;           // 0..3
    const int lane = t & 31;
    const int gid  = lane >> 2;
    const int tig  = lane & 3;
    const int m0   = (wid & 1) * 64;   // warp grid 2(m) x 2(n)
    const int n0w  = (wid >> 1) * 64;

    const uint32_t smA = smem_u32(Asm);
    const uint32_t smB = smem_u32(Bsm);

    float acc[4][8][4];
#pragma unroll
    for (int tm = 0; tm < 4; tm++)
#pragma unroll
        for (int tn = 0; tn < 8; tn++)
#pragma unroll
            for (int q = 0; q < 4; q++) acc[tm][tn][q] = 0.f;

    // ---- prefetch tile 0 (8 cp16 each for A and B per thread) ----
#pragma unroll
    for (int r = 0; r < 8; r++) {
        const int c = t + r * 128;
        const int o = c >> 3, kp = (c & 7) * 4;
        cp16(smA + (uint32_t)(o * APAD + kp) * 4,
             Ab + (size_t)(o0c + o) * 256 + kp);
    }
#pragma unroll
    for (int r = 0; r < 8; r++) {
        const int c = t + r * 128;
        const int k = c >> 5, np = (c & 31) * 4;
        cp16(smB + (uint32_t)(k * BPAD + np) * 4,
             Bb + (size_t)k * N_ + n0c + np);
    }
    CP_COMMIT();

#pragma unroll 2
    for (int kt = 0; kt < 8; kt++) {
        CP_WAIT0();
        __syncthreads();

        if (kt < 7) {
            const int k0 = (kt + 1) * KT_;
            const uint32_t bufo = (uint32_t)((kt + 1) & 1);
            const uint32_t dA = smA + bufo * (ABUF * 4);
            const uint32_t dB = smB + bufo * (BBUF * 4);
#pragma unroll
            for (int r = 0; r < 8; r++) {
                const int c = t + r * 128;
                const int o = c >> 3, kp = (c & 7) * 4;
                cp16(dA + (uint32_t)(o * APAD + kp) * 4,
                     Ab + (size_t)(o0c + o) * 256 + k0 + kp);
            }
#pragma unroll
            for (int r = 0; r < 8; r++) {
                const int c = t + r * 128;
                const int k = c >> 5, np = (c & 31) * 4;
                cp16(dB + (uint32_t)(k * BPAD + np) * 4,
                     Bb + (size_t)(k0 + k) * N_ + n0c + np);
            }
            CP_COMMIT();
        }

        const float* As2 = Asm + (kt & 1) * ABUF;
        const float* Bs2 = Bsm + (kt & 1) * BBUF;

#pragma unroll
        for (int ks = 0; ks < 4; ks++) {
            const int kb = ks * 8;
            // A fragments for 4 m16 tiles (16 regs)
            uint32_t af[4][4];
#pragma unroll
            for (int tm = 0; tm < 4; tm++) {
                const int oa = (m0 + tm * 16 + gid) * APAD;
                const int ob = oa + 8 * APAD;
                af[tm][0] = __float_as_uint(As2[oa + kb + tig]);
                af[tm][1] = __float_as_uint(As2[ob + kb + tig]);
                af[tm][2] = __float_as_uint(As2[oa + kb + tig + 4]);
                af[tm][3] = __float_as_uint(As2[ob + kb + tig + 4]);
            }
#pragma unroll
            for (int tn = 0; tn < 8; tn++) {
                const uint32_t b0 = __float_as_uint(Bs2[(kb + tig) * BPAD + n0w + tn * 8 + gid]);
                const uint32_t b1 = __float_as_uint(Bs2[(kb + tig + 4) * BPAD + n0w + tn * 8 + gid]);
#pragma unroll
                for (int tm = 0; tm < 4; tm++)
                    mma_tf32(acc[tm][tn], af[tm][0], af[tm][1], af[tm][2], af[tm][3], b0, b1);
            }
        }
    }

    const int doexp = expq && (o0c < 256);

#pragma unroll
    for (int tm = 0; tm < 4; tm++) {
        const int o_a = o0c + m0 + tm * 16 + gid;
        const int o_b = o_a + 8;
        const float sc_a = gamma[o_a] * rsqrtf(var[o_a] + EPS_);
        const float sh_a = beta[o_a] - mean[o_a] * sc_a;
        const float sc_b = gamma[o_b] * rsqrtf(var[o_b] + EPS_);
        const float sh_b = beta[o_b] - mean[o_b] * sc_b;
        float rs_a = 0.f, rs_b = 0.f;
#pragma unroll
        for (int tn = 0; tn < 8; tn++) {
            const int n = n0c + n0w + tn * 8 + 2 * tig;
            float2 va, vb;
            va.x = acc[tm][tn][0] * sc_a + sh_a;
            va.y = acc[tm][tn][1] * sc_a + sh_a;
            vb.x = acc[tm][tn][2] * sc_b + sh_b;
            vb.y = acc[tm][tn][3] * sc_b + sh_b;
            if (doexp) {
                va.x = __expf(va.x); va.y = __expf(va.y);
                vb.x = __expf(vb.x); vb.y = __expf(vb.y);
                rs_a += va.x + va.y;
                rs_b += vb.x + vb.y;
                va.x = __uint_as_float(tf32c(va.x));
                va.y = __uint_as_float(tf32c(va.y));
                vb.x = __uint_as_float(tf32c(vb.x));
                vb.y = __uint_as_float(tf32c(vb.y));
            }
            *(float2*)&Ob[(size_t)o_a * N_ + n] = va;
            *(float2*)&Ob[(size_t)o_b * N_ + n] = vb;
        }
        if (doexp) {
            rs_a += __shfl_xor_sync(0xffffffffu, rs_a, 1);
            rs_a += __shfl_xor_sync(0xffffffffu, rs_a, 2);
            rs_b += __shfl_xor_sync(0xffffffffu, rs_b, 1);
            rs_b += __shfl_xor_sync(0xffffffffu, rs_b, 2);
            if (tig == 0) {
                atomicAdd(&ssum[b * C_ + o_a], rs_a);
                atomicAdd(&ssum[b * C_ + o_b], rs_b);
            }
        }
    }
}

// ---------------------------------------------------------------------------
// Pre-round qkv_w to tf32 + zero ctx/ssum accumulators (fused; stream order
// guarantees completion before downstream atomics)
// ---------------------------------------------------------------------------
__global__ __launch_bounds__(256)
void round_w(const float* __restrict__ w)
{
    const int i = blockIdx.x * 256 + threadIdx.x;
    g_wr[i] = __uint_as_float(tf32c(w[i]));
    if (i < B_ * HEADS_ * HD_ * HD_) g_ctx[i] = 0.f;
    if (i < B_ * C_) g_ssum[i] = 0.f;
}

// ---------------------------------------------------------------------------
// ctx split-N with fused k-softmax (atomic reduce into zeroed g_ctx)
// ---------------------------------------------------------------------------
__global__ __launch_bounds__(256)
void ctx_kernel()
{
    const int h = blockIdx.x;
    const int b = blockIdx.y;
    const int n0b = blockIdx.z * 256;
    const float* kp = g_qkv + (size_t)b * O3_ * N_ + (size_t)(C_ + h * HD_) * N_;
    const float* vp = g_qkv + (size_t)b * O3_ * N_ + (size_t)(2 * C_ + h * HD_) * N_;

    __shared__ float ks[128][33];
    __shared__ float vs[128][33];

    const int t = threadIdx.x;
    const int i = t >> 4;
    const int j = t & 15;
    float a00 = 0.f, a01 = 0.f, a10 = 0.f, a11 = 0.f;

    for (int cchunk = 0; cchunk < 2; cchunk++) {
        const int n0 = n0b + cchunk * 128;
#pragma unroll
        for (int s = 0; s < 16; s++) {
            const int l = t + s * 256;
            const int d = l >> 7, nn = l & 127;
            ks[nn][d] = kp[(size_t)d * N_ + n0 + nn];
            vs[nn][d] = vp[(size_t)d * N_ + n0 + nn];
        }
        __syncthreads();

        if (t < 128) {
            float m = -CUDART_INF_F;
#pragma unroll
            for (int d = 0; d < HD_; d++) m = fmaxf(m, ks[t][d]);
            float s = 0.f;
#pragma unroll
            for (int d = 0; d < HD_; d++) { float e = __expf(ks[t][d] - m); ks[t][d] = e; s += e; }
            const float inv = 1.f / s;
#pragma unroll
            for (int d = 0; d < HD_; d++) ks[t][d] *= inv;
        }
        __syncthreads();

#pragma unroll 8
        for (int kk = 0; kk < 128; kk++) {
            const float k0 = ks[kk][2 * i], k1 = ks[kk][2 * i + 1];
            const float v0 = vs[kk][2 * j], v1 = vs[kk][2 * j + 1];
            a00 += k0 * v0; a01 += k0 * v1;
            a10 += k1 * v0; a11 += k1 * v1;
        }
        __syncthreads();
    }

    float* cp = g_ctx + (size_t)((b * HEADS_ + h) * HD_) * HD_;
    atomicAdd(&cp[(2 * i + 0) * HD_ + 2 * j + 0], a00);
    atomicAdd(&cp[(2 * i + 0) * HD_ + 2 * j + 1], a01);
    atomicAdd(&cp[(2 * i + 1) * HD_ + 2 * j + 0], a10);
    atomicAdd(&cp[(2 * i + 1) * HD_ + 2 * j + 1], a11);
}

// ---------------------------------------------------------------------------
// fold: M[b,o,c=h*32+d] = tf32( (1/s_c) * sum_e proj_w[o,h*32+e]*ctx[b,h,d,e] )
// ---------------------------------------------------------------------------
extern __shared__ float fold_sm[];

__global__ __launch_bounds__(256)
void fold_kernel(const float* __restrict__ pw)
{
    const int b  = blockIdx.y;
    const int o0 = blockIdx.x * 32;
    const int t  = threadIdx.x;

    float* ctxT = fold_sm;                 // [h][e][d] padded: 8*32*33
    float* pws  = fold_sm + 8 * 32 * 33;   // [32][256]

    const float* cb = g_ctx + (size_t)b * HEADS_ * HD_ * HD_;
#pragma unroll
    for (int s = 0; s < 32; s++) {
        const int idx = t + s * 256;
        const int h = idx >> 10;
        const int d = (idx >> 5) & 31;
        const int e = idx & 31;
        ctxT[(h * 32 + e) * 33 + d] = cb[idx];
    }
#pragma unroll
    for (int oi = 0; oi < 32; oi++)
        pws[oi * 256 + t] = pw[(size_t)(o0 + oi) * C_ + t];
    __syncthreads();

    const int h = t >> 5, d = t & 31;
    const float invs = 1.f / g_ssum[b * C_ + t];
    const float* ct = &ctxT[h * 32 * 33 + d];
    float* Mb = g_M + ((size_t)b * C_ + o0) * C_;

#pragma unroll 4
    for (int oi = 0; oi < 32; oi++) {
        const float* pr = &pws[oi * 256 + h * HD_];
        float s = 0.f;
#pragma unroll
        for (int e = 0; e < HD_; e++)
            s += pr[e] * ct[e * 33];
        Mb[(size_t)oi * C_ + t] = __uint_as_float(tf32c(s * invs));
    }
}

// ---------------------------------------------------------------------------
extern "C" void kernel_launch(void* const* d_in, const int* in_sizes, int n_in,
                              void* d_out, int out_size)
{
    const float* x          = (const float*)d_in[0];
    const float* qkv_w      = (const float*)d_in[1];
    const float* qkv_gamma  = (const float*)d_in[2];
    const float* qkv_beta   = (const float*)d_in[3];
    const float* qkv_mean   = (const float*)d_in[4];
    const float* qkv_var    = (const float*)d_in[5];
    const float* proj_w     = (const float*)d_in[6];
    const float* proj_gamma = (const float*)d_in[7];
    const float* proj_beta  = (const float*)d_in[8];
    const float* proj_mean  = (const float*)d_in[9];
    const float* proj_var   = (const float*)d_in[10];
    float* out = (float*)d_out;

    void* p;
    cudaGetSymbolAddress(&p, g_qkv);  float* qkv = (float*)p;
    cudaGetSymbolAddress(&p, g_M);    float* Mm = (float*)p;
    cudaGetSymbolAddress(&p, g_ssum); float* ssum = (float*)p;
    cudaGetSymbolAddress(&p, g_wr);   float* wr = (float*)p;

    const int FOLD_SM = (8 * 32 * 33 + 32 * 256) * sizeof(float);
    static int cfg = 0;
    if (!cfg) {
        cudaFuncSetAttribute(fold_kernel, cudaFuncAttributeMaxDynamicSharedMemorySize, FOLD_SM);
        cudaFuncSetAttribute(gemm_tc_bn, cudaFuncAttributeMaxDynamicSharedMemorySize, GSMEM);
        cfg = 1;
    }

    // 0) round weights + zero accumulators (fused)
    round_w<<<O3_ * C_ / 256, 256>>>(qkv_w);

    // 1) QKV GEMM + BN; A pre-rounded; q exp'd (tf32-rounded) + ssum
    gemm_tc_bn<<<dim3(N_ / 128, O3_ / 128, B_), 128, GSMEM>>>(
        wr, 0, x, (long)C_ * N_, qkv, (long)O3_ * N_,
        qkv_gamma, qkv_beta, qkv_mean, qkv_var, 1, ssum);

    // 2) ctx = softmax_d(k) @ v^T
    ctx_kernel<<<dim3(HEADS_, B_, 16), 256>>>();

    // 3) fold proj_w with ctx, col-scaled 1/s_c, tf32-rounded
    fold_kernel<<<dim3(8, B_), 256, FOLD_SM>>>(proj_w);

    // 4) out = M @ exp_q + proj BN
    gemm_tc_bn<<<dim3(N_ / 128, C_ / 128, B_), 128, GSMEM>>>(
        Mm, (long)C_ * C_, qkv, (long)O3_ * N_, out, (long)C_ * N_,
        proj_gamma, proj_beta, proj_mean, proj_var, 0, ssum);
}